// round 3
// baseline (speedup 1.0000x reference)
#include <cuda_runtime.h>
#include <math.h>

// Problem constants
#define B_ 2
#define T_ 2048
#define D_ 1024
#define L_ 4
#define V_ 32000
#define FF_ (4 * D_)

// ---------------- scratch (device globals; no allocations allowed) ----------
__device__ float g_x[B_ * T_ * D_];
__device__ float g_h[B_ * T_ * D_];
__device__ float g_q[B_ * T_ * D_];
__device__ float g_k[B_ * T_ * D_];
__device__ float g_v[B_ * T_ * D_];
__device__ float g_y[B_ * T_ * D_];
__device__ float g_att[B_ * T_ * T_];
__device__ float g_ff[B_ * T_ * FF_];

// ---------------- block reductions (256 threads, 8 warps) -------------------
__device__ __forceinline__ float blk_sum(float v, float* sh) {
    __syncthreads();
    #pragma unroll
    for (int o = 16; o > 0; o >>= 1) v += __shfl_down_sync(0xffffffffu, v, o);
    if ((threadIdx.x & 31) == 0) sh[threadIdx.x >> 5] = v;
    __syncthreads();
    float r = sh[0];
    #pragma unroll
    for (int i = 1; i < 8; i++) r += sh[i];
    return r;
}

__device__ __forceinline__ float blk_max(float v, float* sh) {
    __syncthreads();
    #pragma unroll
    for (int o = 16; o > 0; o >>= 1) v = fmaxf(v, __shfl_down_sync(0xffffffffu, v, o));
    if ((threadIdx.x & 31) == 0) sh[threadIdx.x >> 5] = v;
    __syncthreads();
    float r = sh[0];
    #pragma unroll
    for (int i = 1; i < 8; i++) r = fmaxf(r, sh[i]);
    return r;
}

// ---------------- embedding + positional add --------------------------------
__global__ __launch_bounds__(256) void embed_kernel(
    const int* __restrict__ tok, const float* __restrict__ emb,
    const float* __restrict__ pos, float* __restrict__ x)
{
    int row = blockIdx.x;           // 0 .. B*T-1
    int t = row & (T_ - 1);
    int tk = tok[row];
    int d = threadIdx.x * 4;        // D=1024, 256 threads -> 1 float4 each
    float4 e = *(const float4*)(emb + (long long)tk * D_ + d);
    float4 p = *(const float4*)(pos + (long long)t * D_ + d);
    e.x += p.x; e.y += p.y; e.z += p.z; e.w += p.w;
    *(float4*)(x + (long long)row * D_ + d) = e;
}

// ---------------- LayerNorm over D=1024, one block per row ------------------
__global__ __launch_bounds__(256) void layernorm_kernel(
    const float* __restrict__ x, const float* __restrict__ g,
    const float* __restrict__ b, float* __restrict__ out)
{
    __shared__ float sh[8];
    long long row = blockIdx.x;
    const float* xr = x + row * D_;
    int d = threadIdx.x * 4;
    float4 xv = *(const float4*)(xr + d);
    float s = xv.x + xv.y + xv.z + xv.w;
    float s2 = xv.x * xv.x + xv.y * xv.y + xv.z * xv.z + xv.w * xv.w;
    float sum = blk_sum(s, sh);
    float sumsq = blk_sum(s2, sh);
    float mu = sum * (1.0f / D_);
    float var = sumsq * (1.0f / D_) - mu * mu;
    float inv = rsqrtf(var + 1e-5f);
    float4 gv = *(const float4*)(g + d);
    float4 bv = *(const float4*)(b + d);
    float4 o;
    o.x = (xv.x - mu) * inv * gv.x + bv.x;
    o.y = (xv.y - mu) * inv * gv.y + bv.y;
    o.z = (xv.z - mu) * inv * gv.z + bv.z;
    o.w = (xv.w - mu) * inv * gv.w + bv.w;
    *(float4*)(out + row * D_ + d) = o;
}

// ---------------- causal softmax: one block per (t, b) row ------------------
__global__ __launch_bounds__(256) void softmax_kernel(float* __restrict__ att, float scale)
{
    __shared__ float sh[8];
    int t = blockIdx.x;
    int b = blockIdx.y;
    float* row = att + ((long long)b * T_ + t) * (long long)T_;
    int valid = t + 1;
    int tid = threadIdx.x;

    float m = -1e30f;
    for (int s = tid; s < valid; s += 256) m = fmaxf(m, row[s]);
    m = blk_max(m, sh);

    float sum = 0.f;
    for (int s = tid; s < valid; s += 256) {
        float e = __expf((row[s] - m) * scale);
        row[s] = e;
        sum += e;
    }
    sum = blk_sum(sum, sh);
    float inv = 1.0f / sum;
    for (int s = tid; s < T_; s += 256)
        row[s] = (s < valid) ? row[s] * inv : 0.0f;
}

// ---------------- 128x128x8 register-blocked SGEMM --------------------------
// C[M,N] = A[M,K] @ (TB ? B[N,K]^T : B[K,N])  (+bias)(+relu)(+residual)
// Batched via blockIdx.z with element strides sA/sB/sC/sR.
// Requires M%128==0, N%128==0, K%8==0 (all shapes here satisfy this).
#define BM 128
#define BN 128
#define BK 8

template <bool TB>
__global__ __launch_bounds__(256, 2) void gemm_kernel(
    const float* __restrict__ A, const float* __restrict__ B, float* __restrict__ C,
    int M, int N, int K,
    long long sA, long long sB, long long sC,
    const float* __restrict__ bias,
    const float* __restrict__ res, long long sR,
    int relu, int causal)
{
    int bm = blockIdx.y, bn = blockIdx.x, bz = blockIdx.z;
    if (TB && causal && bn * BN > bm * BM + (BM - 1)) return;   // fully-masked tile

    const float* Ab = A + (long long)bz * sA;
    const float* Bb = B + (long long)bz * sB;
    float* Cb = C + (long long)bz * sC;

    __shared__ float As[BK][BM];
    __shared__ float Bs[BK][BN];

    int tid = threadIdx.x;
    int tx = tid & 15;       // 0..15 -> N direction
    int ty = tid >> 4;       // 0..15 -> M direction

    // A-tile loader (also used for B in TB mode): 128 rows x 8 cols, transposed store
    int lrow = tid >> 1;            // 0..127
    int lq = (tid & 1) * 4;         // 0 or 4
    // B-tile loader (NN): 8 rows x 128 cols, direct store
    int brow = tid >> 5;            // 0..7
    int bcol = (tid & 31) * 4;      // 0..124

    float acc[8][8];
    #pragma unroll
    for (int i = 0; i < 8; i++)
        #pragma unroll
        for (int j = 0; j < 8; j++) acc[i][j] = 0.f;

    for (int k0 = 0; k0 < K; k0 += BK) {
        float4 av = *(const float4*)(Ab + (long long)(bm * BM + lrow) * K + k0 + lq);
        As[lq + 0][lrow] = av.x; As[lq + 1][lrow] = av.y;
        As[lq + 2][lrow] = av.z; As[lq + 3][lrow] = av.w;
        if (TB) {
            float4 bv = *(const float4*)(Bb + (long long)(bn * BN + lrow) * K + k0 + lq);
            Bs[lq + 0][lrow] = bv.x; Bs[lq + 1][lrow] = bv.y;
            Bs[lq + 2][lrow] = bv.z; Bs[lq + 3][lrow] = bv.w;
        } else {
            float4 bv = *(const float4*)(Bb + (long long)(k0 + brow) * N + bn * BN + bcol);
            *(float4*)&Bs[brow][bcol] = bv;
        }
        __syncthreads();

        #pragma unroll
        for (int k = 0; k < BK; k++) {
            float ra[8], rb[8];
            #pragma unroll
            for (int i = 0; i < 8; i++) ra[i] = As[k][ty * 8 + i];
            #pragma unroll
            for (int j = 0; j < 8; j++) rb[j] = Bs[k][tx * 8 + j];
            #pragma unroll
            for (int i = 0; i < 8; i++)
                #pragma unroll
                for (int j = 0; j < 8; j++)
                    acc[i][j] += ra[i] * rb[j];
        }
        __syncthreads();
    }

    int row0 = bm * BM + ty * 8;
    int col0 = bn * BN + tx * 8;
    #pragma unroll
    for (int i = 0; i < 8; i++) {
        long long cbase = (long long)(row0 + i) * N + col0;
        #pragma unroll
        for (int j = 0; j < 8; j++) {
            float v = acc[i][j];
            if (bias) v += bias[col0 + j];
            if (relu) v = fmaxf(v, 0.f);
            if (res)  v += res[(long long)bz * sR + cbase + j];
            Cb[cbase + j] = v;
        }
    }
}

// ---------------- launch -----------------------------------------------------
extern "C" void kernel_launch(void* const* d_in, const int* in_sizes, int n_in,
                              void* d_out, int out_size)
{
    (void)in_sizes; (void)n_in; (void)out_size;
    const int*   tokens = (const int*)  d_in[0];
    const float* emb    = (const float*)d_in[1];
    const float* pos    = (const float*)d_in[2];
    const float* Wq     = (const float*)d_in[3];
    const float* Wk     = (const float*)d_in[4];
    const float* Wv     = (const float*)d_in[5];
    const float* w1     = (const float*)d_in[6];
    const float* b1     = (const float*)d_in[7];
    const float* w2     = (const float*)d_in[8];
    const float* b2     = (const float*)d_in[9];
    const float* g1     = (const float*)d_in[10];
    const float* bln1   = (const float*)d_in[11];
    const float* g2     = (const float*)d_in[12];
    const float* bln2   = (const float*)d_in[13];
    const float* proj_w = (const float*)d_in[14];
    const float* proj_b = (const float*)d_in[15];
    float* out = (float*)d_out;

    float *x, *h, *q, *k, *v, *y, *att, *ff;
    cudaGetSymbolAddress((void**)&x,   g_x);
    cudaGetSymbolAddress((void**)&h,   g_h);
    cudaGetSymbolAddress((void**)&q,   g_q);
    cudaGetSymbolAddress((void**)&k,   g_k);
    cudaGetSymbolAddress((void**)&v,   g_v);
    cudaGetSymbolAddress((void**)&y,   g_y);
    cudaGetSymbolAddress((void**)&att, g_att);
    cudaGetSymbolAddress((void**)&ff,  g_ff);

    const int M = B_ * T_;                    // 4096
    const float scale = 1.0f / sqrtf((float)D_);
    const long long TD = (long long)T_ * D_;
    const long long TT = (long long)T_ * T_;

    embed_kernel<<<M, 256>>>(tokens, emb, pos, x);

    for (int l = 0; l < L_; l++) {
        const float* wq = Wq + (long long)l * D_ * D_;
        const float* wk = Wk + (long long)l * D_ * D_;
        const float* wv = Wv + (long long)l * D_ * D_;

        layernorm_kernel<<<M, 256>>>(x, g1 + l * D_, bln1 + l * D_, h);

        dim3 gqkv(D_ / BN, M / BM);
        gemm_kernel<false><<<gqkv, 256>>>(h, wq, q, M, D_, D_, 0, 0, 0, nullptr, nullptr, 0, 0, 0);
        gemm_kernel<false><<<gqkv, 256>>>(h, wk, k, M, D_, D_, 0, 0, 0, nullptr, nullptr, 0, 0, 0);
        gemm_kernel<false><<<gqkv, 256>>>(h, wv, v, M, D_, D_, 0, 0, 0, nullptr, nullptr, 0, 0, 0);

        // scores[b] = Q[b] @ K[b]^T  (causal tiles only)
        dim3 gsc(T_ / BN, T_ / BM, B_);
        gemm_kernel<true><<<gsc, 256>>>(q, k, att, T_, T_, D_, TD, TD, TT,
                                        nullptr, nullptr, 0, 0, 1);

        softmax_kernel<<<dim3(T_, B_), 256>>>(att, scale);

        // x = att @ V + x   (residual fused in epilogue)
        dim3 gav(D_ / BN, T_ / BM, B_);
        gemm_kernel<false><<<gav, 256>>>(att, v, x, T_, D_, T_, TT, TD, TD,
                                         nullptr, x, TD, 0, 0);

        layernorm_kernel<<<M, 256>>>(x, g2 + l * D_, bln2 + l * D_, y);

        // ff = relu(y @ w1 + b1)
        dim3 gf1(FF_ / BN, M / BM);
        gemm_kernel<false><<<gf1, 256>>>(y, w1 + (long long)l * D_ * FF_, ff,
                                         M, FF_, D_, 0, 0, 0,
                                         b1 + (long long)l * FF_, nullptr, 0, 1, 0);
        // x = ff @ w2 + b2 + y
        dim3 gf2(D_ / BN, M / BM);
        gemm_kernel<false><<<gf2, 256>>>(ff, w2 + (long long)l * FF_ * D_, x,
                                         M, D_, FF_, 0, 0, 0,
                                         b2 + (long long)l * D_, y, 0, 0, 0);
    }

    // logits = x @ proj_w + proj_b
    dim3 gp(V_ / BN, M / BM);
    gemm_kernel<false><<<gp, 256>>>(x, proj_w, out, M, V_, D_, 0, 0, 0,
                                    proj_b, nullptr, 0, 0, 0);
}

// round 4
// speedup vs baseline: 2.9492x; 2.9492x over previous
#include <cuda_runtime.h>
#include <math.h>
#include <stdint.h>

// Problem constants
#define B_ 2
#define T_ 2048
#define D_ 1024
#define L_ 4
#define V_ 32000
#define FF_ (4 * D_)

// ---------------- scratch (device globals; no allocations allowed) ----------
__device__ float g_x[B_ * T_ * D_];
__device__ float g_h[B_ * T_ * D_];
__device__ float g_q[B_ * T_ * D_];
__device__ float g_k[B_ * T_ * D_];
__device__ float g_v[B_ * T_ * D_];
__device__ float g_y[B_ * T_ * D_];
__device__ float g_att[B_ * T_ * T_];
__device__ float g_ff[B_ * T_ * FF_];

// ---------------- block reductions (256 threads, 8 warps) -------------------
__device__ __forceinline__ float blk_sum(float v, float* sh) {
    __syncthreads();
    #pragma unroll
    for (int o = 16; o > 0; o >>= 1) v += __shfl_down_sync(0xffffffffu, v, o);
    if ((threadIdx.x & 31) == 0) sh[threadIdx.x >> 5] = v;
    __syncthreads();
    float r = sh[0];
    #pragma unroll
    for (int i = 1; i < 8; i++) r += sh[i];
    return r;
}

__device__ __forceinline__ float blk_max(float v, float* sh) {
    __syncthreads();
    #pragma unroll
    for (int o = 16; o > 0; o >>= 1) v = fmaxf(v, __shfl_down_sync(0xffffffffu, v, o));
    if ((threadIdx.x & 31) == 0) sh[threadIdx.x >> 5] = v;
    __syncthreads();
    float r = sh[0];
    #pragma unroll
    for (int i = 1; i < 8; i++) r = fmaxf(r, sh[i]);
    return r;
}

// ---------------- embedding + positional add --------------------------------
__global__ __launch_bounds__(256) void embed_kernel(
    const int* __restrict__ tok, const float* __restrict__ emb,
    const float* __restrict__ pos, float* __restrict__ x)
{
    int row = blockIdx.x;
    int t = row & (T_ - 1);
    int tk = tok[row];
    int d = threadIdx.x * 4;
    float4 e = *(const float4*)(emb + (long long)tk * D_ + d);
    float4 p = *(const float4*)(pos + (long long)t * D_ + d);
    e.x += p.x; e.y += p.y; e.z += p.z; e.w += p.w;
    *(float4*)(x + (long long)row * D_ + d) = e;
}

// ---------------- LayerNorm over D=1024, one block per row ------------------
__global__ __launch_bounds__(256) void layernorm_kernel(
    const float* __restrict__ x, const float* __restrict__ g,
    const float* __restrict__ b, float* __restrict__ out)
{
    __shared__ float sh[8];
    long long row = blockIdx.x;
    const float* xr = x + row * D_;
    int d = threadIdx.x * 4;
    float4 xv = *(const float4*)(xr + d);
    float s = xv.x + xv.y + xv.z + xv.w;
    float s2 = xv.x * xv.x + xv.y * xv.y + xv.z * xv.z + xv.w * xv.w;
    float sum = blk_sum(s, sh);
    float sumsq = blk_sum(s2, sh);
    float mu = sum * (1.0f / D_);
    float var = sumsq * (1.0f / D_) - mu * mu;
    float inv = rsqrtf(var + 1e-5f);
    float4 gv = *(const float4*)(g + d);
    float4 bv = *(const float4*)(b + d);
    float4 o;
    o.x = (xv.x - mu) * inv * gv.x + bv.x;
    o.y = (xv.y - mu) * inv * gv.y + bv.y;
    o.z = (xv.z - mu) * inv * gv.z + bv.z;
    o.w = (xv.w - mu) * inv * gv.w + bv.w;
    *(float4*)(out + row * D_ + d) = o;
}

// ---------------- causal softmax: one block per (t, b) row ------------------
__global__ __launch_bounds__(256) void softmax_kernel(float* __restrict__ att, float scale)
{
    __shared__ float sh[8];
    int t = blockIdx.x;
    int b = blockIdx.y;
    float* row = att + ((long long)b * T_ + t) * (long long)T_;
    int valid = t + 1;
    int tid = threadIdx.x;

    float m = -1e30f;
    for (int s = tid; s < valid; s += 256) m = fmaxf(m, row[s]);
    m = blk_max(m, sh);

    float sum = 0.f;
    for (int s = tid; s < valid; s += 256) {
        float e = __expf((row[s] - m) * scale);
        row[s] = e;
        sum += e;
    }
    sum = blk_sum(sum, sh);
    float inv = 1.0f / sum;
    for (int s = tid; s < T_; s += 256)
        row[s] = (s < valid) ? row[s] * inv : 0.0f;
}

// =====================  tf32 tensor-core GEMM  ===============================
// C[M,N] = A[M,K] @ (TB ? B[N,K]^T : B[K,N])  (+bias)(+relu)(+residual)
// CTA tile 128x128x16, 8 warps (warp tile 64x32), mma.m16n8k8.tf32,
// 2-stage cp.async pipeline, conflict-free padded smem.
#define BM 128
#define BN 128
#define BK 16
#define ASTR 28    // A smem row stride (floats): 112B rows, 16B aligned, bank-clean
#define BSTR 136   // B smem row stride (floats): 544B rows, 16B aligned, bank-clean

__device__ __forceinline__ uint32_t f2tf(float f) {
    uint32_t u;
    asm("cvt.rna.tf32.f32 %0, %1;" : "=r"(u) : "f"(f));
    return u;
}

__device__ __forceinline__ void mma_tf32(float* c,
    uint32_t a0, uint32_t a1, uint32_t a2, uint32_t a3, uint32_t b0, uint32_t b1)
{
    asm volatile(
        "mma.sync.aligned.m16n8k8.row.col.f32.tf32.tf32.f32 "
        "{%0,%1,%2,%3}, {%4,%5,%6,%7}, {%8,%9}, {%0,%1,%2,%3};"
        : "+f"(c[0]), "+f"(c[1]), "+f"(c[2]), "+f"(c[3])
        : "r"(a0), "r"(a1), "r"(a2), "r"(a3), "r"(b0), "r"(b1));
}

__device__ __forceinline__ void cp_async16(float* smem, const float* gmem) {
    uint32_t s = (uint32_t)__cvta_generic_to_shared(smem);
    asm volatile("cp.async.ca.shared.global [%0], [%1], 16;" :: "r"(s), "l"(gmem));
}

template <bool TB>
__global__ __launch_bounds__(256, 2) void gemm_tc(
    const float* __restrict__ A, const float* __restrict__ B, float* __restrict__ C,
    int M, int N, int K,
    long long sA, long long sB, long long sC,
    const float* __restrict__ bias,
    const float* __restrict__ res, long long sR,
    int relu, int causal)
{
    int bm = blockIdx.y, bn = blockIdx.x, bz = blockIdx.z;
    if (TB && causal && bn * BN > bm * BM + (BM - 1)) return;  // fully masked tile

    const float* Ab = A + (long long)bz * sA;
    const float* Bb = B + (long long)bz * sB;
    float* Cb = C + (long long)bz * sC;

    __shared__ __align__(16) float As[2][BM * ASTR];
    __shared__ __align__(16) float Bs[2][BK * BSTR];

    int tid = threadIdx.x;
    int lane = tid & 31, warp = tid >> 5;
    int g = lane >> 2, tig = lane & 3;
    int wm = (warp >> 2) * 64;    // warp m offset (0,64)
    int wn = (warp & 3) * 32;     // warp n offset (0,32,64,96)

    // A tile loader: 128 rows x 16 floats; thread -> row tid>>1, 8 floats at (tid&1)*8
    int a_row = tid >> 1;
    int a_k = (tid & 1) * 8;
    const float* a_g = Ab + (long long)(bm * BM + a_row) * K + a_k;
    int a_soff = a_row * ASTR + a_k;

    // B NN loader: 16 rows x 128 floats; thread -> k row tid>>4, 8 floats at (tid&15)*8
    int b_k = tid >> 4;
    int b_n = (tid & 15) * 8;
    const float* b_g = Bb + (long long)b_k * N + bn * BN + b_n;
    int b_soff = b_k * BSTR + b_n;

    // B TB loader (transpose): thread -> n row tid>>1, 8 k-floats at (tid&1)*8
    int bt_n = tid >> 1;
    int bt_k = (tid & 1) * 8;
    const float* bt_g = TB ? (Bb + (long long)(bn * BN + bt_n) * K + bt_k) : nullptr;

    float acc[4][4][4];
    #pragma unroll
    for (int mi = 0; mi < 4; mi++)
        #pragma unroll
        for (int ni = 0; ni < 4; ni++)
            #pragma unroll
            for (int j = 0; j < 4; j++) acc[mi][ni][j] = 0.f;

    int nK = K / BK;

    // ---- stage 0 prologue ----
    {
        cp_async16(&As[0][a_soff],     a_g);
        cp_async16(&As[0][a_soff + 4], a_g + 4);
        if (TB) {
            float4 v0 = *(const float4*)(bt_g);
            float4 v1 = *(const float4*)(bt_g + 4);
            float* bs = &Bs[0][0];
            bs[(bt_k + 0) * BSTR + bt_n] = v0.x;
            bs[(bt_k + 1) * BSTR + bt_n] = v0.y;
            bs[(bt_k + 2) * BSTR + bt_n] = v0.z;
            bs[(bt_k + 3) * BSTR + bt_n] = v0.w;
            bs[(bt_k + 4) * BSTR + bt_n] = v1.x;
            bs[(bt_k + 5) * BSTR + bt_n] = v1.y;
            bs[(bt_k + 6) * BSTR + bt_n] = v1.z;
            bs[(bt_k + 7) * BSTR + bt_n] = v1.w;
        } else {
            cp_async16(&Bs[0][b_soff],     b_g);
            cp_async16(&Bs[0][b_soff + 4], b_g + 4);
        }
        asm volatile("cp.async.commit_group;");
    }

    for (int ks = 0; ks < nK; ks++) {
        int st = ks & 1;
        asm volatile("cp.async.wait_group 0;");
        __syncthreads();

        if (ks + 1 < nK) {
            int st2 = st ^ 1;
            long long k0 = (long long)(ks + 1) * BK;
            cp_async16(&As[st2][a_soff],     a_g + k0);
            cp_async16(&As[st2][a_soff + 4], a_g + k0 + 4);
            if (TB) {
                float4 v0 = *(const float4*)(bt_g + k0);
                float4 v1 = *(const float4*)(bt_g + k0 + 4);
                float* bs = &Bs[st2][0];
                bs[(bt_k + 0) * BSTR + bt_n] = v0.x;
                bs[(bt_k + 1) * BSTR + bt_n] = v0.y;
                bs[(bt_k + 2) * BSTR + bt_n] = v0.z;
                bs[(bt_k + 3) * BSTR + bt_n] = v0.w;
                bs[(bt_k + 4) * BSTR + bt_n] = v1.x;
                bs[(bt_k + 5) * BSTR + bt_n] = v1.y;
                bs[(bt_k + 6) * BSTR + bt_n] = v1.z;
                bs[(bt_k + 7) * BSTR + bt_n] = v1.w;
            } else {
                cp_async16(&Bs[st2][b_soff],     b_g + k0 * N);
                cp_async16(&Bs[st2][b_soff + 4], b_g + k0 * N + 4);
            }
            asm volatile("cp.async.commit_group;");
        }

        #pragma unroll
        for (int kk = 0; kk < BK; kk += 8) {
            uint32_t af[4][4], bf[4][2];
            #pragma unroll
            for (int mi = 0; mi < 4; mi++) {
                const float* ap = &As[st][(wm + mi * 16 + g) * ASTR + kk + tig];
                af[mi][0] = f2tf(ap[0]);
                af[mi][1] = f2tf(ap[8 * ASTR]);
                af[mi][2] = f2tf(ap[4]);
                af[mi][3] = f2tf(ap[8 * ASTR + 4]);
            }
            #pragma unroll
            for (int ni = 0; ni < 4; ni++) {
                const float* bp = &Bs[st][(kk + tig) * BSTR + wn + ni * 8 + g];
                bf[ni][0] = f2tf(bp[0]);
                bf[ni][1] = f2tf(bp[4 * BSTR]);
            }
            #pragma unroll
            for (int mi = 0; mi < 4; mi++)
                #pragma unroll
                for (int ni = 0; ni < 4; ni++)
                    mma_tf32(acc[mi][ni], af[mi][0], af[mi][1], af[mi][2], af[mi][3],
                             bf[ni][0], bf[ni][1]);
        }
        __syncthreads();
    }

    // ---- epilogue: fragment layout c0,c1 = (row g, cols 2t,2t+1); c2,c3 = row g+8
    #pragma unroll
    for (int mi = 0; mi < 4; mi++) {
        int r0 = bm * BM + wm + mi * 16 + g;
        #pragma unroll
        for (int ni = 0; ni < 4; ni++) {
            int c0 = bn * BN + wn + ni * 8 + 2 * tig;
            float* cf = acc[mi][ni];
            float bx = 0.f, by = 0.f;
            if (bias) { bx = bias[c0]; by = bias[c0 + 1]; }
            // row r0
            {
                float vx = cf[0] + bx, vy = cf[1] + by;
                if (relu) { vx = fmaxf(vx, 0.f); vy = fmaxf(vy, 0.f); }
                long long off = (long long)r0 * N + c0;
                if (res) { vx += res[(long long)bz * sR + off]; vy += res[(long long)bz * sR + off + 1]; }
                *(float2*)(Cb + off) = make_float2(vx, vy);
            }
            // row r0 + 8
            {
                float vx = cf[2] + bx, vy = cf[3] + by;
                if (relu) { vx = fmaxf(vx, 0.f); vy = fmaxf(vy, 0.f); }
                long long off = (long long)(r0 + 8) * N + c0;
                if (res) { vx += res[(long long)bz * sR + off]; vy += res[(long long)bz * sR + off + 1]; }
                *(float2*)(Cb + off) = make_float2(vx, vy);
            }
        }
    }
}

// ---------------- launch -----------------------------------------------------
extern "C" void kernel_launch(void* const* d_in, const int* in_sizes, int n_in,
                              void* d_out, int out_size)
{
    (void)in_sizes; (void)n_in; (void)out_size;
    const int*   tokens = (const int*)  d_in[0];
    const float* emb    = (const float*)d_in[1];
    const float* pos    = (const float*)d_in[2];
    const float* Wq     = (const float*)d_in[3];
    const float* Wk     = (const float*)d_in[4];
    const float* Wv     = (const float*)d_in[5];
    const float* w1     = (const float*)d_in[6];
    const float* b1     = (const float*)d_in[7];
    const float* w2     = (const float*)d_in[8];
    const float* b2     = (const float*)d_in[9];
    const float* g1     = (const float*)d_in[10];
    const float* bln1   = (const float*)d_in[11];
    const float* g2     = (const float*)d_in[12];
    const float* bln2   = (const float*)d_in[13];
    const float* proj_w = (const float*)d_in[14];
    const float* proj_b = (const float*)d_in[15];
    float* out = (float*)d_out;

    float *x, *h, *q, *k, *v, *y, *att, *ff;
    cudaGetSymbolAddress((void**)&x,   g_x);
    cudaGetSymbolAddress((void**)&h,   g_h);
    cudaGetSymbolAddress((void**)&q,   g_q);
    cudaGetSymbolAddress((void**)&k,   g_k);
    cudaGetSymbolAddress((void**)&v,   g_v);
    cudaGetSymbolAddress((void**)&y,   g_y);
    cudaGetSymbolAddress((void**)&att, g_att);
    cudaGetSymbolAddress((void**)&ff,  g_ff);

    const int M = B_ * T_;                    // 4096
    const float scale = 1.0f / sqrtf((float)D_);
    const long long TD = (long long)T_ * D_;
    const long long TT = (long long)T_ * T_;

    embed_kernel<<<M, 256>>>(tokens, emb, pos, x);

    for (int l = 0; l < L_; l++) {
        const float* wq = Wq + (long long)l * D_ * D_;
        const float* wk = Wk + (long long)l * D_ * D_;
        const float* wv = Wv + (long long)l * D_ * D_;

        layernorm_kernel<<<M, 256>>>(x, g1 + l * D_, bln1 + l * D_, h);

        dim3 gqkv(D_ / BN, M / BM);
        gemm_tc<false><<<gqkv, 256>>>(h, wq, q, M, D_, D_, 0, 0, 0, nullptr, nullptr, 0, 0, 0);
        gemm_tc<false><<<gqkv, 256>>>(h, wk, k, M, D_, D_, 0, 0, 0, nullptr, nullptr, 0, 0, 0);
        gemm_tc<false><<<gqkv, 256>>>(h, wv, v, M, D_, D_, 0, 0, 0, nullptr, nullptr, 0, 0, 0);

        // scores[b] = Q[b] @ K[b]^T  (causal tiles only)
        dim3 gsc(T_ / BN, T_ / BM, B_);
        gemm_tc<true><<<gsc, 256>>>(q, k, att, T_, T_, D_, TD, TD, TT,
                                    nullptr, nullptr, 0, 0, 1);

        softmax_kernel<<<dim3(T_, B_), 256>>>(att, scale);

        // x = att @ V + x   (residual fused)
        dim3 gav(D_ / BN, T_ / BM, B_);
        gemm_tc<false><<<gav, 256>>>(att, v, x, T_, D_, T_, TT, TD, TD,
                                     nullptr, x, TD, 0, 0);

        layernorm_kernel<<<M, 256>>>(x, g2 + l * D_, bln2 + l * D_, y);

        // ff = relu(y @ w1 + b1)
        dim3 gf1(FF_ / BN, M / BM);
        gemm_tc<false><<<gf1, 256>>>(y, w1 + (long long)l * D_ * FF_, ff,
                                     M, FF_, D_, 0, 0, 0,
                                     b1 + (long long)l * FF_, nullptr, 0, 1, 0);
        // x = ff @ w2 + b2 + y
        dim3 gf2(D_ / BN, M / BM);
        gemm_tc<false><<<gf2, 256>>>(ff, w2 + (long long)l * FF_ * D_, x,
                                     M, D_, FF_, 0, 0, 0,
                                     b2 + (long long)l * D_, y, 0, 0, 0);
    }

    // logits = x @ proj_w + proj_b
    dim3 gp(V_ / BN, M / BM);
    gemm_tc<false><<<gp, 256>>>(x, proj_w, out, M, V_, D_, 0, 0, 0,
                                proj_b, nullptr, 0, 0, 0);
}